// round 15
// baseline (speedup 1.0000x reference)
#include <cuda_runtime.h>

// ---------------------------------------------------------------------------
// AttentionSeq2SeqModel: B=512, S=14, H=128, IN=1, target_len=8
// out = [B,8,1] outputs then [B,14,1] total_attn (fp32).
//
// R15: 128 CTAs x 512 threads (4 warps/SMSP), 4 rows/CTA, IN-WARP split-K=4.
// tid = q*4 + p: thread computes the k in [32p,32p+32) partial of unit q's
// 4 gates x 4 rows. Partials reduced by a 2-stage shfl butterfly (xor2,xor1)
// -> ONE __syncthreads per LSTM step. Each thread finalizes 1 cell (row p,
// unit q). Weights: 8 k-rows/quarter in regs (32 regs), 24 via smem slots
// (stride 100, conflict-free). h quarters at stride 40 (banks 0/8/16/24).
// MUFU.TANH activations. Packed fma.rn.f32x2 mainloop.
// ---------------------------------------------------------------------------

#define B_    512
#define S_    14
#define H_    128
#define NG    512
#define R_    4
#define TPB   512
#define NCTA  128
#define KRH   8           // k-rows per quarter in registers
#define KSH   24          // k-rows per quarter in smem
#define WSTR  100         // weight slot stride (floats): 4*KSH=96 + pad
#define HQS   40          // h quarter stride (banks 0/8/16/24 across p)
#define HRS   160         // h row stride = 4*HQS
#define TLEN  8

typedef unsigned long long u64;

__device__ float g_enc[B_ * S_ * H_];
__device__ float g_encProj[B_ * S_ * H_];

union F2U { float2 f; u64 u; };

__device__ __forceinline__ void fma2(u64 &acc, u64 a, u64 b) {
    asm("fma.rn.f32x2 %0, %1, %2, %0;" : "+l"(acc) : "l"(a), "l"(b));
}
__device__ __forceinline__ float tanh_(float x) {
    float r;
    asm("tanh.approx.f32 %0, %1;" : "=f"(r) : "f"(x));
    return r;
}
__device__ __forceinline__ float sigm(float x) {
    float r;
    asm("tanh.approx.f32 %0, %1;" : "=f"(r) : "f"(x * 0.5f));
    return fmaf(0.5f, r, 0.5f);
}
__device__ __forceinline__ float warpsum(float v) {
    v += __shfl_xor_sync(0xffffffffu, v, 16);
    v += __shfl_xor_sync(0xffffffffu, v, 8);
    v += __shfl_xor_sync(0xffffffffu, v, 4);
    v += __shfl_xor_sync(0xffffffffu, v, 2);
    v += __shfl_xor_sync(0xffffffffu, v, 1);
    return v;
}
// h element index within a row: quarter-padded layout
__device__ __forceinline__ int hidx(int k) { return (k >> 5) * HQS + (k & 31); }

// Wsm[(q*4+p)*WSTR + c*KSH + i] = W[p*32 + KRH + i][c*128 + q]
__device__ __forceinline__ void stage_w(float* __restrict__ Wsm,
                                        const float* __restrict__ W, int tid) {
    for (int idx = tid; idx < 4 * 128 * 128; idx += TPB) {
        int qq = idx & 127;
        int k  = (idx >> 7) & 127;
        int c  = idx >> 14;
        int kl = k & 31;
        if (kl >= KRH) {
            int pp = k >> 5;
            Wsm[(qq * 4 + pp) * WSTR + c * KSH + (kl - KRH)] =
                W[(size_t)k * NG + c * 128 + qq];
        }
    }
}

// register weights: k in [32p, 32p+KRH), packed (k,k+1) f32x2, per gate c
__device__ __forceinline__ void load_tail(u64 wrp[4][KRH / 2],
                                          const float* __restrict__ W,
                                          int p, int q) {
#pragma unroll
    for (int c = 0; c < 4; c++) {
        const int col = c * 128 + q;
#pragma unroll
        for (int j = 0; j < KRH / 2; j++) {
            F2U v;
            int k = p * 32 + 2 * j;
            v.f.x = __ldg(W + (size_t)k * NG + col);
            v.f.y = __ldg(W + (size_t)(k + 1) * NG + col);
            wrp[c][j] = v.u;
        }
    }
}

// Quarter-partial gate GEMV: g[c][m] = b_c + x_m*wih_c + sum_{k in quarter} h W
// (bb/wih pre-zeroed on p>0 lanes -> no divergence.)
__device__ __forceinline__ void gate_gemv(
    const float* __restrict__ hsR,
    const float* __restrict__ Wsm, int tid, int p,
    const u64 wrp[4][KRH / 2],
    const float bb[4], const float wih[4],
    float x0, float x1, float x2, float x3,
    float g[4][4])
{
    u64 acc[4][4];
    F2U t;
    float xv[4] = {x0, x1, x2, x3};
#pragma unroll
    for (int c = 0; c < 4; c++)
#pragma unroll
        for (int m = 0; m < 4; m++) {
            t.f = make_float2(fmaf(xv[m], wih[c], bb[c]), 0.f);
            acc[c][m] = t.u;
        }

    const float* hf0 = hsR + 0 * HRS + p * HQS;
    const float* hf1 = hsR + 1 * HRS + p * HQS;
    const float* hf2 = hsR + 2 * HRS + p * HQS;
    const float* hf3 = hsR + 3 * HRS + p * HQS;

    // register-weight part: local k in [0, KRH)
#pragma unroll
    for (int i = 0; i < KRH / 4; i++) {
        ulonglong2 h0 = *reinterpret_cast<const ulonglong2*>(hf0 + 4 * i);
        ulonglong2 h1 = *reinterpret_cast<const ulonglong2*>(hf1 + 4 * i);
        ulonglong2 h2 = *reinterpret_cast<const ulonglong2*>(hf2 + 4 * i);
        ulonglong2 h3 = *reinterpret_cast<const ulonglong2*>(hf3 + 4 * i);
#pragma unroll
        for (int c = 0; c < 4; c++) {
            u64 wa = wrp[c][2 * i], wb = wrp[c][2 * i + 1];
            fma2(acc[c][0], h0.x, wa); fma2(acc[c][0], h0.y, wb);
            fma2(acc[c][1], h1.x, wa); fma2(acc[c][1], h1.y, wb);
            fma2(acc[c][2], h2.x, wa); fma2(acc[c][2], h2.y, wb);
            fma2(acc[c][3], h3.x, wa); fma2(acc[c][3], h3.y, wb);
        }
    }

    // smem-weight part: local k in [KRH, 32)
    const float* w0 = Wsm + tid * WSTR;
    const float* w1 = w0 + KSH;
    const float* w2 = w0 + 2 * KSH;
    const float* w3 = w0 + 3 * KSH;
#pragma unroll
    for (int i = 0; i < KSH / 4; i++) {
        ulonglong2 wv0 = *reinterpret_cast<const ulonglong2*>(w0 + 4 * i);
        ulonglong2 wv1 = *reinterpret_cast<const ulonglong2*>(w1 + 4 * i);
        ulonglong2 wv2 = *reinterpret_cast<const ulonglong2*>(w2 + 4 * i);
        ulonglong2 wv3 = *reinterpret_cast<const ulonglong2*>(w3 + 4 * i);
        const int ko = KRH + 4 * i;
        ulonglong2 h0 = *reinterpret_cast<const ulonglong2*>(hf0 + ko);
        ulonglong2 h1 = *reinterpret_cast<const ulonglong2*>(hf1 + ko);
        ulonglong2 h2 = *reinterpret_cast<const ulonglong2*>(hf2 + ko);
        ulonglong2 h3 = *reinterpret_cast<const ulonglong2*>(hf3 + ko);
        fma2(acc[0][0], h0.x, wv0.x); fma2(acc[0][0], h0.y, wv0.y);
        fma2(acc[0][1], h1.x, wv0.x); fma2(acc[0][1], h1.y, wv0.y);
        fma2(acc[0][2], h2.x, wv0.x); fma2(acc[0][2], h2.y, wv0.y);
        fma2(acc[0][3], h3.x, wv0.x); fma2(acc[0][3], h3.y, wv0.y);
        fma2(acc[1][0], h0.x, wv1.x); fma2(acc[1][0], h0.y, wv1.y);
        fma2(acc[1][1], h1.x, wv1.x); fma2(acc[1][1], h1.y, wv1.y);
        fma2(acc[1][2], h2.x, wv1.x); fma2(acc[1][2], h2.y, wv1.y);
        fma2(acc[1][3], h3.x, wv1.x); fma2(acc[1][3], h3.y, wv1.y);
        fma2(acc[2][0], h0.x, wv2.x); fma2(acc[2][0], h0.y, wv2.y);
        fma2(acc[2][1], h1.x, wv2.x); fma2(acc[2][1], h1.y, wv2.y);
        fma2(acc[2][2], h2.x, wv2.x); fma2(acc[2][2], h2.y, wv2.y);
        fma2(acc[2][3], h3.x, wv2.x); fma2(acc[2][3], h3.y, wv2.y);
        fma2(acc[3][0], h0.x, wv3.x); fma2(acc[3][0], h0.y, wv3.y);
        fma2(acc[3][1], h1.x, wv3.x); fma2(acc[3][1], h1.y, wv3.y);
        fma2(acc[3][2], h2.x, wv3.x); fma2(acc[3][2], h2.y, wv3.y);
        fma2(acc[3][3], h3.x, wv3.x); fma2(acc[3][3], h3.y, wv3.y);
    }
#pragma unroll
    for (int c = 0; c < 4; c++)
#pragma unroll
        for (int m = 0; m < 4; m++) {
            t.u = acc[c][m];
            g[c][m] = t.f.x + t.f.y;
        }
}

// In-warp 4-way butterfly reduction + elementwise + h store.
// Thread (q,p) finalizes cell (row p, unit q).
__device__ __forceinline__ float lstm_tail(
    float g[4][4], int p, int hwpos, float &creg,
    float* __restrict__ hsW)
{
    const int pr  = p & 2;        // my pair's rows {pr, pr+1}
    const int opr = 2 - pr;       // other pair's rows
    // stage 1 (xor 2): send other-pair rows, accumulate my-pair rows
#pragma unroll
    for (int c = 0; c < 4; c++)
#pragma unroll
        for (int r = 0; r < 2; r++) {
            float send = g[c][opr + r];
            float recv = __shfl_xor_sync(0xffffffffu, send, 2);
            g[c][pr + r] += recv;
        }
    // stage 2 (xor 1): send partner's row, accumulate mine
    const int pp = p ^ 1;
#pragma unroll
    for (int c = 0; c < 4; c++) {
        float send = g[c][pp];
        float recv = __shfl_xor_sync(0xffffffffu, send, 1);
        g[c][p] += recv;
    }
    float gi = g[0][p], gf = g[1][p], gg = g[2][p], go = g[3][p];
    float cn = sigm(gf) * creg + sigm(gi) * tanh_(gg);
    creg = cn;
    float h = sigm(go) * tanh_(cn);
    hsW[hwpos] = h;
    return h;
}

__global__ __launch_bounds__(TPB, 1)
void seq2seq_kernel(
    const float* __restrict__ inputs,
    const float* __restrict__ Wih_e, const float* __restrict__ Whh_e, const float* __restrict__ b_e,
    const float* __restrict__ Wih_d, const float* __restrict__ Whh_d, const float* __restrict__ b_d,
    const float* __restrict__ We,    const float* __restrict__ Wd,
    const float* __restrict__ Wv,    const float* __restrict__ Wf,    const float* __restrict__ bf,
    float* __restrict__ out, int write_attn)
{
    extern __shared__ float smf[];
    float* Wsm     = smf;                      // 512*WSTR = 51200
    float* hsA     = Wsm + 512 * WSTR;         // 4*HRS = 640
    float* hsB     = hsA + R_ * HRS;           // 640
    float* ctx     = hsB + R_ * HRS;           // 512
    float* xs      = ctx + R_ * H_;            // 4
    float* xenc    = xs + R_;                  // 56
    float* attn    = xenc + R_ * S_;           // 56
    float* attnAcc = attn + R_ * S_;           // 56
    float* red     = attnAcc + R_ * S_;        // 224
    // total 53388 floats = 213552 B

    const int tid  = threadIdx.x;
    const int lane = tid & 31;
    const int wg   = (tid >> 5) & 3;
    const int cta  = blockIdx.x;
    const int q    = tid >> 2;      // unit
    const int p    = tid & 3;       // k-quarter; finalizes (row p, unit q)
    const int hwpos = p * HRS + (q >> 5) * HQS + (q & 31);  // h write position

    u64 wrp[4][KRH / 2];
    float bb[4], wih[4];

    // ---- init + stage encoder weights ----
    stage_w(Wsm, Whh_e, tid);
    load_tail(wrp, Whh_e, p, q);
    if (tid < R_ * S_) {
        attnAcc[tid] = 0.f;
        int mm = tid / S_, tt = tid - mm * S_;
        xenc[tid] = inputs[(cta * R_ + mm) * S_ + tt];
    }
    if (tid < R_) xs[tid] = inputs[(cta * R_ + tid) * S_ + (S_ - 1)];
    for (int idx = tid; idx < 2 * R_ * HRS; idx += TPB) hsA[idx] = 0.f;

    float creg = 0.f;
    float* hsR = hsA;
    float* hsW = hsB;

#pragma unroll
    for (int c = 0; c < 4; c++) {
        bb[c]  = (p == 0) ? b_e[c * 128 + q]   : 0.f;
        wih[c] = (p == 0) ? Wih_e[c * 128 + q] : 0.f;
    }
    const int jm = tid & 127;       // role index for attention phases
    const int pm = tid >> 7;
    const float wv_j = Wv[jm];
    const float wf_j = Wf[jm];
    const float bf0  = bf[0];
    __syncthreads();

    // ================= Encoder: 14 steps =================
    for (int t = 0; t < S_; t++) {
        float x0 = xenc[0 * S_ + t], x1 = xenc[1 * S_ + t];
        float x2 = xenc[2 * S_ + t], x3 = xenc[3 * S_ + t];
        float g[4][4];
        gate_gemv(hsR, Wsm, tid, p, wrp, bb, wih, x0, x1, x2, x3, g);
        float h = lstm_tail(g, p, hwpos, creg, hsW);
        g_enc[((size_t)(cta * R_ + p)) * S_ * H_ + t * H_ + q] = h;
        __syncthreads();
        float* tmp = hsR; hsR = hsW; hsW = tmp;
    }

    // ---- restage for decoder ----
    stage_w(Wsm, Whh_d, tid);
    load_tail(wrp, Whh_d, p, q);
#pragma unroll
    for (int c = 0; c < 4; c++) {
        bb[c]  = (p == 0) ? b_d[c * 128 + q]   : 0.f;
        wih[c] = (p == 0) ? Wih_d[c * 128 + q] : 0.f;
    }

    // ---- encProj[t][j] = sum_k enc[t][k] * We[k][j] (once; reused 8x) ----
    {
        int m = pm, jj = jm;
        const float* eb = g_enc + ((size_t)(cta * R_ + m)) * S_ * H_;
        float acc[S_];
#pragma unroll
        for (int t = 0; t < S_; t++) acc[t] = 0.f;
#pragma unroll 4
        for (int k = 0; k < H_; k++) {
            float we = __ldg(We + k * H_ + jj);
#pragma unroll
            for (int t = 0; t < S_; t++) acc[t] += __ldg(eb + t * H_ + k) * we;
        }
        float* pb = g_encProj + ((size_t)(cta * R_ + m)) * S_ * H_;
#pragma unroll
        for (int t = 0; t < S_; t++) pb[t * H_ + jj] = acc[t];
    }
    __syncthreads();

    // ================= Decoder: 8 steps =================
    for (int s = 0; s < TLEN; s++) {
        // hWd[m][j] = h[m] @ Wd  (1 cell per thread; quarter-padded h reads)
        {
            int m = pm, jj = jm;
            const float* hrow = hsR + m * HRS;
            float acc = 0.f;
#pragma unroll
            for (int qt = 0; qt < 4; qt++)
#pragma unroll 8
                for (int kk = 0; kk < 32; kk++)
                    acc += hrow[qt * HQS + kk] * __ldg(Wd + (qt * 32 + kk) * H_ + jj);
            ctx[m * H_ + jj] = acc;
        }
        __syncthreads();

        // scores[m][t] = sum_j tanh(encProj + hWd) * Wv  (m = pm)
        {
            int m = pm;
            float hwd = ctx[m * H_ + jm];
            const float* ep = g_encProj + ((size_t)(cta * R_ + m)) * S_ * H_;
#pragma unroll
            for (int t = 0; t < S_; t++) {
                float v = tanh_(ep[t * H_ + jm] + hwd) * wv_j;
                v = warpsum(v);
                if (lane == 0) red[(m * S_ + t) * 4 + wg] = v;
            }
        }
        __syncthreads();
        if (tid < R_ * S_) {
            int b4 = tid * 4;
            attn[tid] = red[b4] + red[b4 + 1] + red[b4 + 2] + red[b4 + 3];
        }
        __syncthreads();
        if (tid < R_) {
            float mx = attn[tid * S_];
#pragma unroll
            for (int t = 1; t < S_; t++) mx = fmaxf(mx, attn[tid * S_ + t]);
            float ssum = 0.f, ex[S_];
#pragma unroll
            for (int t = 0; t < S_; t++) { ex[t] = __expf(attn[tid * S_ + t] - mx); ssum += ex[t]; }
            float inv = __fdividef(1.f, ssum);
#pragma unroll
            for (int t = 0; t < S_; t++) {
                float a_ = ex[t] * inv;
                attn[tid * S_ + t] = a_;
                attnAcc[tid * S_ + t] += a_;
            }
        }
        __syncthreads();
        // context[m][j] = sum_t attn * enc  (1 cell per thread)
        {
            int m = pm, jj = jm;
            const float* eb = g_enc + ((size_t)(cta * R_ + m)) * S_ * H_;
            float acc = 0.f;
#pragma unroll
            for (int t = 0; t < S_; t++) acc += attn[m * S_ + t] * __ldg(eb + t * H_ + jj);
            ctx[m * H_ + jj] = acc;
        }
        __syncthreads();

        // inner decoder LSTM: 129 scalar-input steps, ONE barrier each
        for (int js = 0; js < H_ + 1; js++) {
            float x0, x1, x2, x3;
            if (js < H_) {
                x0 = ctx[js]; x1 = ctx[H_ + js];
                x2 = ctx[2 * H_ + js]; x3 = ctx[3 * H_ + js];
            } else {
                x0 = xs[0]; x1 = xs[1]; x2 = xs[2]; x3 = xs[3];
            }
            float g[4][4];
            gate_gemv(hsR, Wsm, tid, p, wrp, bb, wih, x0, x1, x2, x3, g);
            lstm_tail(g, p, hwpos, creg, hsW);
            __syncthreads();
            float* tmp = hsR; hsR = hsW; hsW = tmp;
        }

        // out = h @ Wf + bf ; feed back as next x
        {
            float v = hsR[pm * HRS + hidx(jm)] * wf_j;
            v = warpsum(v);
            if (lane == 0) red[pm * 4 + wg] = v;
        }
        __syncthreads();
        if (tid < R_) {
            float o = red[tid * 4] + red[tid * 4 + 1] + red[tid * 4 + 2] + red[tid * 4 + 3] + bf0;
            out[(cta * R_ + tid) * TLEN + s] = o;
            xs[tid] = o;
        }
        __syncthreads();
    }

    if (write_attn && tid < R_ * S_)
        out[B_ * TLEN + (cta * R_ + tid / S_) * S_ + (tid % S_)] = attnAcc[tid];
}

extern "C" void kernel_launch(void* const* d_in, const int* in_sizes, int n_in,
                              void* d_out, int out_size) {
    const float* inputs = (const float*)d_in[0];
    const int off = (n_in >= 13 && in_sizes[1] == 1) ? 2 : 1;
    const float* Wih_e = (const float*)d_in[off + 0];
    const float* Whh_e = (const float*)d_in[off + 1];
    const float* b_e   = (const float*)d_in[off + 2];
    const float* Wih_d = (const float*)d_in[off + 3];
    const float* Whh_d = (const float*)d_in[off + 4];
    const float* b_d   = (const float*)d_in[off + 5];
    const float* We    = (const float*)d_in[off + 6];
    const float* Wd    = (const float*)d_in[off + 7];
    const float* Wv    = (const float*)d_in[off + 8];
    const float* Wf    = (const float*)d_in[off + 9];
    const float* bf    = (const float*)d_in[off + 10];

    const int smem_floats = 512 * WSTR + 2 * R_ * HRS + R_ * H_
                          + R_ + 3 * R_ * S_ + R_ * S_ * 4;
    const int smem_bytes = smem_floats * (int)sizeof(float);  // 213552

    cudaFuncSetAttribute(seq2seq_kernel,
                         cudaFuncAttributeMaxDynamicSharedMemorySize, smem_bytes);

    const int write_attn = (out_size >= B_ * TLEN + B_ * S_) ? 1 : 0;

    seq2seq_kernel<<<NCTA, TPB, smem_bytes>>>(
        inputs, Wih_e, Whh_e, b_e, Wih_d, Whh_d, b_d,
        We, Wd, Wv, Wf, bf, (float*)d_out, write_attn);
}

// round 16
// speedup vs baseline: 2.7122x; 2.7122x over previous
#include <cuda_runtime.h>

// ---------------------------------------------------------------------------
// AttentionSeq2SeqModel: B=512, S=14, H=128, IN=1, target_len=8
// out = [B,8,1] outputs then [B,14,1] total_attn (fp32).
//
// R16: R14 structure unchanged (256 thr, in-warp split-K=2, one barrier/step,
// shfl exchange, padded h rows, KRH=28 reg k-rows + KSH=36 smem k-rows,
// MUFU.TANH activations) + PHASE-SWAPPED WARP PAIRS: warps 4-7 execute the
// smem-weight GEMV part before the register-weight part, so each SMSP's two
// warps hit their LDS-dependent stall pockets out of phase — the reg-part
// (pure FMA, no load deps) of one warp fills the other's load stalls.
// ---------------------------------------------------------------------------

#define B_    512
#define S_    14
#define H_    128
#define NG    512
#define R_    4
#define TPB   256
#define NCTA  128
#define KRH   28          // k-rows per half in registers
#define KSH   36          // k-rows per half in smem
#define WSTR  36          // weight slot stride
#define HSTR  132         // padded h row stride; half-B at +68 (bank delta 4)
#define TLEN  8

typedef unsigned long long u64;

__device__ float g_enc[B_ * S_ * H_];
__device__ float g_encProj[B_ * S_ * H_];

union F2U { float2 f; u64 u; };

__device__ __forceinline__ void fma2(u64 &acc, u64 a, u64 b) {
    asm("fma.rn.f32x2 %0, %1, %2, %0;" : "+l"(acc) : "l"(a), "l"(b));
}
__device__ __forceinline__ float tanh_(float x) {
    float r;
    asm("tanh.approx.f32 %0, %1;" : "=f"(r) : "f"(x));
    return r;
}
__device__ __forceinline__ float sigm(float x) {
    float r;
    asm("tanh.approx.f32 %0, %1;" : "=f"(r) : "f"(x * 0.5f));
    return fmaf(0.5f, r, 0.5f);
}
__device__ __forceinline__ float warpsum(float v) {
    v += __shfl_xor_sync(0xffffffffu, v, 16);
    v += __shfl_xor_sync(0xffffffffu, v, 8);
    v += __shfl_xor_sync(0xffffffffu, v, 4);
    v += __shfl_xor_sync(0xffffffffu, v, 2);
    v += __shfl_xor_sync(0xffffffffu, v, 1);
    return v;
}

// Wsm[(c*256 + t)*WSTR + i] = W[(t&1)*64 + KRH + i][c*128 + (t>>1)], i<KSH
__device__ __forceinline__ void stage_w(float* __restrict__ Wsm,
                                        const float* __restrict__ W, int tid) {
    for (int idx = tid; idx < 1024 * KSH; idx += TPB) {
        int i    = idx >> 10;
        int slot = idx & 1023;
        int c = slot >> 8;
        int t = slot & 255;
        int k = (t & 1) * 64 + KRH + i;
        int col = c * 128 + (t >> 1);
        Wsm[slot * WSTR + i] = W[(size_t)k * NG + col];
    }
}

// register weights: k in [64p, 64p+KRH), packed (k,k+1) f32x2, per gate c
__device__ __forceinline__ void load_tail(u64 wrp[4][KRH / 2],
                                          const float* __restrict__ W,
                                          int p, int q) {
#pragma unroll
    for (int c = 0; c < 4; c++) {
        const int col = c * 128 + q;
#pragma unroll
        for (int j = 0; j < KRH / 2; j++) {
            F2U v;
            int k = p * 64 + 2 * j;
            v.f.x = __ldg(W + (size_t)k * NG + col);
            v.f.y = __ldg(W + (size_t)(k + 1) * NG + col);
            wrp[c][j] = v.u;
        }
    }
}

// ---- GEMV phases (shared by both orderings) ----
__device__ __forceinline__ void gemv_reg_part(
    u64 acc[4][4],
    const float* hf0, const float* hf1, const float* hf2, const float* hf3,
    const u64 wrp[4][KRH / 2])
{
#pragma unroll
    for (int i = 0; i < KRH / 4; i++) {
        ulonglong2 h0 = *reinterpret_cast<const ulonglong2*>(hf0 + 4 * i);
        ulonglong2 h1 = *reinterpret_cast<const ulonglong2*>(hf1 + 4 * i);
        ulonglong2 h2 = *reinterpret_cast<const ulonglong2*>(hf2 + 4 * i);
        ulonglong2 h3 = *reinterpret_cast<const ulonglong2*>(hf3 + 4 * i);
#pragma unroll
        for (int c = 0; c < 4; c++) {
            u64 wa = wrp[c][2 * i], wb = wrp[c][2 * i + 1];
            fma2(acc[c][0], h0.x, wa); fma2(acc[c][0], h0.y, wb);
            fma2(acc[c][1], h1.x, wa); fma2(acc[c][1], h1.y, wb);
            fma2(acc[c][2], h2.x, wa); fma2(acc[c][2], h2.y, wb);
            fma2(acc[c][3], h3.x, wa); fma2(acc[c][3], h3.y, wb);
        }
    }
}

__device__ __forceinline__ void gemv_smem_part(
    u64 acc[4][4],
    const float* hf0, const float* hf1, const float* hf2, const float* hf3,
    const float* w0, const float* w1, const float* w2, const float* w3)
{
#pragma unroll
    for (int i = 0; i < KSH / 4; i++) {
        ulonglong2 wv0 = *reinterpret_cast<const ulonglong2*>(w0 + 4 * i);
        ulonglong2 wv1 = *reinterpret_cast<const ulonglong2*>(w1 + 4 * i);
        ulonglong2 wv2 = *reinterpret_cast<const ulonglong2*>(w2 + 4 * i);
        ulonglong2 wv3 = *reinterpret_cast<const ulonglong2*>(w3 + 4 * i);
        const int ko = KRH + 4 * i;
        ulonglong2 h0 = *reinterpret_cast<const ulonglong2*>(hf0 + ko);
        ulonglong2 h1 = *reinterpret_cast<const ulonglong2*>(hf1 + ko);
        ulonglong2 h2 = *reinterpret_cast<const ulonglong2*>(hf2 + ko);
        ulonglong2 h3 = *reinterpret_cast<const ulonglong2*>(hf3 + ko);
        fma2(acc[0][0], h0.x, wv0.x); fma2(acc[0][0], h0.y, wv0.y);
        fma2(acc[0][1], h1.x, wv0.x); fma2(acc[0][1], h1.y, wv0.y);
        fma2(acc[0][2], h2.x, wv0.x); fma2(acc[0][2], h2.y, wv0.y);
        fma2(acc[0][3], h3.x, wv0.x); fma2(acc[0][3], h3.y, wv0.y);
        fma2(acc[1][0], h0.x, wv1.x); fma2(acc[1][0], h0.y, wv1.y);
        fma2(acc[1][1], h1.x, wv1.x); fma2(acc[1][1], h1.y, wv1.y);
        fma2(acc[1][2], h2.x, wv1.x); fma2(acc[1][2], h2.y, wv1.y);
        fma2(acc[1][3], h3.x, wv1.x); fma2(acc[1][3], h3.y, wv1.y);
        fma2(acc[2][0], h0.x, wv2.x); fma2(acc[2][0], h0.y, wv2.y);
        fma2(acc[2][1], h1.x, wv2.x); fma2(acc[2][1], h1.y, wv2.y);
        fma2(acc[2][2], h2.x, wv2.x); fma2(acc[2][2], h2.y, wv2.y);
        fma2(acc[2][3], h3.x, wv2.x); fma2(acc[2][3], h3.y, wv2.y);
        fma2(acc[3][0], h0.x, wv3.x); fma2(acc[3][0], h0.y, wv3.y);
        fma2(acc[3][1], h1.x, wv3.x); fma2(acc[3][1], h1.y, wv3.y);
        fma2(acc[3][2], h2.x, wv3.x); fma2(acc[3][2], h2.y, wv3.y);
        fma2(acc[3][3], h3.x, wv3.x); fma2(acc[3][3], h3.y, wv3.y);
    }
}

// Half-partial gate GEMV; `swp` (warp-uniform) selects phase order so the
// two warps sharing an SMSP stall out of phase.
__device__ __forceinline__ void gate_gemv(
    const float* __restrict__ hsR, int hoff,     // hoff = p*68
    const float* __restrict__ Wsm, int tid, bool swp,
    const u64 wrp[4][KRH / 2],
    const float bb[4], const float wih[4],
    float x0, float x1, float x2, float x3,
    float g[4][4])
{
    u64 acc[4][4];
    F2U t;
    float xv[4] = {x0, x1, x2, x3};
#pragma unroll
    for (int c = 0; c < 4; c++)
#pragma unroll
        for (int m = 0; m < 4; m++) {
            t.f = make_float2(fmaf(xv[m], wih[c], bb[c]), 0.f);
            acc[c][m] = t.u;
        }

    const float* hf0 = hsR + 0 * HSTR + hoff;
    const float* hf1 = hsR + 1 * HSTR + hoff;
    const float* hf2 = hsR + 2 * HSTR + hoff;
    const float* hf3 = hsR + 3 * HSTR + hoff;
    const float* w0 = Wsm + (0 * 256 + tid) * WSTR;
    const float* w1 = Wsm + (1 * 256 + tid) * WSTR;
    const float* w2 = Wsm + (2 * 256 + tid) * WSTR;
    const float* w3 = Wsm + (3 * 256 + tid) * WSTR;

    if (swp) {
        gemv_smem_part(acc, hf0, hf1, hf2, hf3, w0, w1, w2, w3);
        gemv_reg_part(acc, hf0, hf1, hf2, hf3, wrp);
    } else {
        gemv_reg_part(acc, hf0, hf1, hf2, hf3, wrp);
        gemv_smem_part(acc, hf0, hf1, hf2, hf3, w0, w1, w2, w3);
    }
#pragma unroll
    for (int c = 0; c < 4; c++)
#pragma unroll
        for (int m = 0; m < 4; m++) {
            t.u = acc[c][m];
            g[c][m] = t.f.x + t.f.y;
        }
}

// In-warp exchange + elementwise + h store for one LSTM step.
// p==0 lanes finalize rows 0,1; p==1 lanes rows 2,3.
__device__ __forceinline__ void lstm_tail(
    float g[4][4], int p, int qpos, float creg[2],
    float* __restrict__ hsW, float hout[2])
{
#pragma unroll
    for (int c = 0; c < 4; c++)
#pragma unroll
        for (int r = 0; r < 2; r++) {
            float send = p ? g[c][r] : g[c][2 + r];
            float recv = __shfl_xor_sync(0xffffffffu, send, 1);
            if (p) g[c][2 + r] += recv; else g[c][r] += recv;
        }
#pragma unroll
    for (int mi = 0; mi < 2; mi++) {
        float gi = p ? g[0][2 + mi] : g[0][mi];
        float gf = p ? g[1][2 + mi] : g[1][mi];
        float gg = p ? g[2][2 + mi] : g[2][mi];
        float go = p ? g[3][2 + mi] : g[3][mi];
        float c = sigm(gf) * creg[mi] + sigm(gi) * tanh_(gg);
        creg[mi] = c;
        float h = sigm(go) * tanh_(c);
        hout[mi] = h;
        hsW[(2 * p + mi) * HSTR + qpos] = h;
    }
}

__global__ __launch_bounds__(TPB, 1)
void seq2seq_kernel(
    const float* __restrict__ inputs,
    const float* __restrict__ Wih_e, const float* __restrict__ Whh_e, const float* __restrict__ b_e,
    const float* __restrict__ Wih_d, const float* __restrict__ Whh_d, const float* __restrict__ b_d,
    const float* __restrict__ We,    const float* __restrict__ Wd,
    const float* __restrict__ Wv,    const float* __restrict__ Wf,    const float* __restrict__ bf,
    float* __restrict__ out, int write_attn)
{
    extern __shared__ float smf[];
    float* Wsm     = smf;                      // 1024*WSTR = 36864
    float* hsA     = Wsm + 1024 * WSTR;        // 4*HSTR = 528
    float* hsB     = hsA + R_ * HSTR;          // 528
    float* ctx     = hsB + R_ * HSTR;          // 512
    float* xs      = ctx + R_ * H_;            // 4
    float* xenc    = xs + R_;                  // 56
    float* attn    = xenc + R_ * S_;           // 56
    float* attnAcc = attn + R_ * S_;           // 56
    float* red     = attnAcc + R_ * S_;        // 224
    // total 38828 floats = 155312 B

    const int tid  = threadIdx.x;
    const int lane = tid & 31;
    const int wg   = (tid >> 5) & 3;
    const int cta  = blockIdx.x;
    const int q    = tid >> 1;      // unit
    const int p    = tid & 1;       // k-half; finalizes rows 2p, 2p+1
    const int hoff = p * 68;        // h half offset (padded layout)
    const int qpos = q + (q >= 64 ? 4 : 0);
    const bool swp = (tid >= 128);  // warps 4-7: smem-part first (phase swap)

    u64 wrp[4][KRH / 2];
    float bb[4], wih[4];

    // ---- init + stage encoder weights ----
    stage_w(Wsm, Whh_e, tid);
    load_tail(wrp, Whh_e, p, q);
    if (tid < R_ * S_) {
        attnAcc[tid] = 0.f;
        int mm = tid / S_, tt = tid - mm * S_;
        xenc[tid] = inputs[(cta * R_ + mm) * S_ + tt];
    }
    if (tid < R_) xs[tid] = inputs[(cta * R_ + tid) * S_ + (S_ - 1)];
    for (int idx = tid; idx < 2 * R_ * HSTR; idx += TPB) hsA[idx] = 0.f;

    float creg[2] = {0.f, 0.f};
    float* hsR = hsA;
    float* hsW = hsB;

#pragma unroll
    for (int c = 0; c < 4; c++) {
        bb[c]  = p ? 0.f : b_e[c * 128 + q];
        wih[c] = p ? 0.f : Wih_e[c * 128 + q];
    }
    const int jm = tid & 127;       // role index for attention phases
    const int pm = tid >> 7;
    const float wv_j = Wv[jm];
    const float wf_j = Wf[jm];
    const float bf0  = bf[0];
    __syncthreads();

    // ================= Encoder: 14 steps =================
    for (int t = 0; t < S_; t++) {
        float x0 = xenc[0 * S_ + t], x1 = xenc[1 * S_ + t];
        float x2 = xenc[2 * S_ + t], x3 = xenc[3 * S_ + t];
        float g[4][4];
        gate_gemv(hsR, hoff, Wsm, tid, swp, wrp, bb, wih, x0, x1, x2, x3, g);
        float hout[2];
        lstm_tail(g, p, qpos, creg, hsW, hout);
#pragma unroll
        for (int mi = 0; mi < 2; mi++)
            g_enc[((size_t)(cta * R_ + 2 * p + mi)) * S_ * H_ + t * H_ + q] = hout[mi];
        __syncthreads();
        float* tmp = hsR; hsR = hsW; hsW = tmp;
    }

    // ---- restage for decoder ----
    stage_w(Wsm, Whh_d, tid);
    load_tail(wrp, Whh_d, p, q);
#pragma unroll
    for (int c = 0; c < 4; c++) {
        bb[c]  = p ? 0.f : b_d[c * 128 + q];
        wih[c] = p ? 0.f : Wih_d[c * 128 + q];
    }

    // ---- encProj[t][j] = sum_k enc[t][k] * We[k][j] (once; reused 8x) ----
    for (int cell = tid; cell < R_ * H_; cell += TPB) {
        int m = cell >> 7, jj = cell & 127;
        const float* eb = g_enc + ((size_t)(cta * R_ + m)) * S_ * H_;
        float acc[S_];
#pragma unroll
        for (int t = 0; t < S_; t++) acc[t] = 0.f;
#pragma unroll 4
        for (int k = 0; k < H_; k++) {
            float we = __ldg(We + k * H_ + jj);
#pragma unroll
            for (int t = 0; t < S_; t++) acc[t] += __ldg(eb + t * H_ + k) * we;
        }
        float* pb = g_encProj + ((size_t)(cta * R_ + m)) * S_ * H_;
#pragma unroll
        for (int t = 0; t < S_; t++) pb[t * H_ + jj] = acc[t];
    }
    __syncthreads();

    // ================= Decoder: 8 steps =================
    for (int s = 0; s < TLEN; s++) {
        // hWd[m][j] = h[m] @ Wd  (padded h reads)
        for (int cell = tid; cell < R_ * H_; cell += TPB) {
            int m = cell >> 7, jj = cell & 127;
            const float* hrow = hsR + m * HSTR;
            float acc = 0.f;
#pragma unroll 8
            for (int k = 0; k < 64; k++)
                acc += hrow[k] * __ldg(Wd + k * H_ + jj);
#pragma unroll 8
            for (int k = 64; k < H_; k++)
                acc += hrow[k + 4] * __ldg(Wd + k * H_ + jj);
            ctx[cell] = acc;
        }
        __syncthreads();

        // scores[m][t] = sum_j tanh(encProj + hWd) * Wv
#pragma unroll
        for (int pass = 0; pass < 2; pass++) {
            int m = pm + 2 * pass;
            float hwd = ctx[m * H_ + jm];
            const float* ep = g_encProj + ((size_t)(cta * R_ + m)) * S_ * H_;
#pragma unroll
            for (int t = 0; t < S_; t++) {
                float v = tanh_(ep[t * H_ + jm] + hwd) * wv_j;
                v = warpsum(v);
                if (lane == 0) red[(m * S_ + t) * 4 + wg] = v;
            }
        }
        __syncthreads();
        if (tid < R_ * S_) {
            int b4 = tid * 4;
            attn[tid] = red[b4] + red[b4 + 1] + red[b4 + 2] + red[b4 + 3];
        }
        __syncthreads();
        if (tid < R_) {
            float mx = attn[tid * S_];
#pragma unroll
            for (int t = 1; t < S_; t++) mx = fmaxf(mx, attn[tid * S_ + t]);
            float ssum = 0.f, ex[S_];
#pragma unroll
            for (int t = 0; t < S_; t++) { ex[t] = __expf(attn[tid * S_ + t] - mx); ssum += ex[t]; }
            float inv = __fdividef(1.f, ssum);
#pragma unroll
            for (int t = 0; t < S_; t++) {
                float a_ = ex[t] * inv;
                attn[tid * S_ + t] = a_;
                attnAcc[tid * S_ + t] += a_;
            }
        }
        __syncthreads();
        // context[m][j] = sum_t attn * enc
        for (int cell = tid; cell < R_ * H_; cell += TPB) {
            int m = cell >> 7, jj = cell & 127;
            const float* eb = g_enc + ((size_t)(cta * R_ + m)) * S_ * H_;
            float acc = 0.f;
#pragma unroll
            for (int t = 0; t < S_; t++) acc += attn[m * S_ + t] * __ldg(eb + t * H_ + jj);
            ctx[cell] = acc;
        }
        __syncthreads();

        // inner decoder LSTM: 129 scalar-input steps, ONE barrier each
        for (int js = 0; js < H_ + 1; js++) {
            float x0, x1, x2, x3;
            if (js < H_) {
                x0 = ctx[js]; x1 = ctx[H_ + js];
                x2 = ctx[2 * H_ + js]; x3 = ctx[3 * H_ + js];
            } else {
                x0 = xs[0]; x1 = xs[1]; x2 = xs[2]; x3 = xs[3];
            }
            float g[4][4];
            gate_gemv(hsR, hoff, Wsm, tid, swp, wrp, bb, wih, x0, x1, x2, x3, g);
            float hout[2];
            lstm_tail(g, p, qpos, creg, hsW, hout);
            __syncthreads();
            float* tmp = hsR; hsR = hsW; hsW = tmp;
        }

        // out = h @ Wf + bf ; feed back as next x
#pragma unroll
        for (int pass = 0; pass < 2; pass++) {
            int m = pm + 2 * pass;
            float v = hsR[m * HSTR + jm + (jm >= 64 ? 4 : 0)] * wf_j;
            v = warpsum(v);
            if (lane == 0) red[m * 4 + wg] = v;
        }
        __syncthreads();
        if (tid < R_) {
            float o = red[tid * 4] + red[tid * 4 + 1] + red[tid * 4 + 2] + red[tid * 4 + 3] + bf0;
            out[(cta * R_ + tid) * TLEN + s] = o;
            xs[tid] = o;
        }
        __syncthreads();
    }

    if (write_attn && tid < R_ * S_)
        out[B_ * TLEN + (cta * R_ + tid / S_) * S_ + (tid % S_)] = attnAcc[tid];
}

extern "C" void kernel_launch(void* const* d_in, const int* in_sizes, int n_in,
                              void* d_out, int out_size) {
    const float* inputs = (const float*)d_in[0];
    const int off = (n_in >= 13 && in_sizes[1] == 1) ? 2 : 1;
    const float* Wih_e = (const float*)d_in[off + 0];
    const float* Whh_e = (const float*)d_in[off + 1];
    const float* b_e   = (const float*)d_in[off + 2];
    const float* Wih_d = (const float*)d_in[off + 3];
    const float* Whh_d = (const float*)d_in[off + 4];
    const float* b_d   = (const float*)d_in[off + 5];
    const float* We    = (const float*)d_in[off + 6];
    const float* Wd    = (const float*)d_in[off + 7];
    const float* Wv    = (const float*)d_in[off + 8];
    const float* Wf    = (const float*)d_in[off + 9];
    const float* bf    = (const float*)d_in[off + 10];

    const int smem_floats = 1024 * WSTR + 2 * R_ * HSTR + R_ * H_
                          + R_ + 3 * R_ * S_ + R_ * S_ * 4;
    const int smem_bytes = smem_floats * (int)sizeof(float);  // 155312

    cudaFuncSetAttribute(seq2seq_kernel,
                         cudaFuncAttributeMaxDynamicSharedMemorySize, smem_bytes);

    const int write_attn = (out_size >= B_ * TLEN + B_ * S_) ? 1 : 0;

    seq2seq_kernel<<<NCTA, TPB, smem_bytes>>>(
        inputs, Wih_e, Whh_e, b_e, Wih_d, Whh_d, b_d,
        We, Wd, Wv, Wf, bf, (float*)d_out, write_attn);
}